// round 5
// baseline (speedup 1.0000x reference)
#include <cuda_runtime.h>
#include <cuda_fp16.h>

#define NROWS 8192
#define NHEAD 4

// scratch (static device globals; no allocation in kernel_launch)
__device__ __half     g_support16[NROWS * 256];   // 4 MB, [n][h*64+o] fp16
__device__ float      g_f1[NROWS * NHEAD];        // [n][h]
__device__ float      g_f2[NROWS * NHEAD];        // [n][h]
__device__ unsigned   g_gmax_u[NHEAD];            // ordered-uint per-head max f1
__device__ float      g_E1[NROWS * 8];            // [m][h][{E1p,E1n}]
__device__ float      g_rowc[NROWS * 16];         // [n][h][{F2p,F2n,T,pad}]

__device__ __forceinline__ unsigned f_enc(float f) {
    unsigned b = __float_as_uint(f);
    return (b & 0x80000000u) ? ~b : (b | 0x80000000u);
}
__device__ __forceinline__ float f_dec(unsigned u) {
    return __uint_as_float((u & 0x80000000u) ? (u & 0x7FFFFFFFu) : ~u);
}

__global__ void init_kernel() {
    if (threadIdx.x < NHEAD) g_gmax_u[threadIdx.x] = 0u;
}

// ---- packed fp32x2 helpers (Blackwell FFMA2 via PTX) ----------------------
__device__ __forceinline__ void ffma2(unsigned long long& d,
                                      unsigned long long a, unsigned long long b) {
    asm("fma.rn.f32x2 %0, %1, %2, %0;" : "+l"(d) : "l"(a), "l"(b));
}
__device__ __forceinline__ unsigned long long pack2(float x) {
    unsigned long long r; unsigned u = __float_as_uint(x);
    asm("mov.b64 %0, {%1, %1};" : "=l"(r) : "r"(u));
    return r;
}
__device__ __forceinline__ float2 unpack2(unsigned long long v) {
    unsigned a, b;
    asm("mov.b64 {%0, %1}, %2;" : "=r"(a), "=r"(b) : "l"(v));
    return make_float2(__uint_as_float(a), __uint_as_float(b));
}

// ---------------------------------------------------------------------------
// GEMM: C[8192,256] = A[8192,256] @ op(B)[256,256], 64x128 tiles, 256 thr.
// Thread: 4 rows x 8 cols as 4 f32x2 pairs; math via fma.rn.f32x2.
//   TRANSB=0: op(B)=B. Epilogue: fp16 support, f1/f2 via 8-lane shfl, gmax.
//   TRANSB=1: op(B)=B^T. Writes C + bias1 + bias2 (residual base).
// ---------------------------------------------------------------------------
template <int TRANSB>
__global__ __launch_bounds__(256) void gemm_kernel(
    const float* __restrict__ A, const float* __restrict__ B,
    const float* __restrict__ bias1, const float* __restrict__ bias2,
    const float* __restrict__ wu, const float* __restrict__ wv,
    float* __restrict__ C)
{
    __shared__ __align__(16) float As[64][17];
    __shared__ __align__(16) float Bs[16][132];
    const int tid = threadIdx.x;
    const int r0 = blockIdx.y * 64;
    const int c0 = blockIdx.x * 128;
    const int tx = tid & 15, ty = tid >> 4;

    unsigned long long acc2[4][4];
#pragma unroll
    for (int i = 0; i < 4; i++)
#pragma unroll
        for (int j = 0; j < 4; j++) acc2[i][j] = 0ull;

    for (int kk = 0; kk < 256; kk += 16) {
#pragma unroll
        for (int i = 0; i < 4; i++) {
            int e = tid + i * 256;
            As[e >> 4][e & 15] = A[(size_t)(r0 + (e >> 4)) * 256 + kk + (e & 15)];
        }
#pragma unroll
        for (int i = 0; i < 8; i++) {
            int e = tid + i * 256;
            if (TRANSB) {
                int c = e >> 4, k = e & 15;
                Bs[k][c] = B[(size_t)(c0 + c) * 256 + kk + k];
            } else {
                int k = e >> 7, c = e & 127;
                Bs[k][c] = B[(size_t)(kk + k) * 256 + c0 + c];
            }
        }
        __syncthreads();
#pragma unroll
        for (int k = 0; k < 16; k++) {
            const ulonglong2* bp = (const ulonglong2*)&Bs[k][tx * 8];
            ulonglong2 bA = bp[0], bB = bp[1];
#pragma unroll
            for (int i = 0; i < 4; i++) {
                unsigned long long a2 = pack2(As[ty * 4 + i][k]);
                ffma2(acc2[i][0], a2, bA.x);
                ffma2(acc2[i][1], a2, bA.y);
                ffma2(acc2[i][2], a2, bB.x);
                ffma2(acc2[i][3], a2, bB.y);
            }
        }
        __syncthreads();
    }

    const int cg = c0 + tx * 8;
    if (TRANSB) {
        float bsum[8];
#pragma unroll
        for (int j = 0; j < 8; j++) bsum[j] = bias1[cg + j] + bias2[cg + j];
#pragma unroll
        for (int i = 0; i < 4; i++) {
            int r = r0 + ty * 4 + i;
            float2 p0 = unpack2(acc2[i][0]), p1 = unpack2(acc2[i][1]);
            float2 p2 = unpack2(acc2[i][2]), p3 = unpack2(acc2[i][3]);
            float4 o0 = make_float4(p0.x + bsum[0], p0.y + bsum[1],
                                    p1.x + bsum[2], p1.y + bsum[3]);
            float4 o1 = make_float4(p2.x + bsum[4], p2.y + bsum[5],
                                    p3.x + bsum[6], p3.y + bsum[7]);
            *(float4*)&C[(size_t)r * 256 + cg] = o0;
            *(float4*)&C[(size_t)r * 256 + cg + 4] = o1;
        }
    } else {
        const int h = blockIdx.x * 2 + (tx >> 3);
        float w1[8], w2[8];
#pragma unroll
        for (int j = 0; j < 8; j++) { w1[j] = wu[cg + j]; w2[j] = wv[cg + j]; }
        float mloc = -3.0e38f;
#pragma unroll
        for (int i = 0; i < 4; i++) {
            int r = r0 + ty * 4 + i;
            float c[8];
            float2 q;
            q = unpack2(acc2[i][0]); c[0] = q.x; c[1] = q.y;
            q = unpack2(acc2[i][1]); c[2] = q.x; c[3] = q.y;
            q = unpack2(acc2[i][2]); c[4] = q.x; c[5] = q.y;
            q = unpack2(acc2[i][3]); c[6] = q.x; c[7] = q.y;
            union { __half2 hh[4]; float4 f; } cv;
            cv.hh[0] = __floats2half2_rn(c[0], c[1]);
            cv.hh[1] = __floats2half2_rn(c[2], c[3]);
            cv.hh[2] = __floats2half2_rn(c[4], c[5]);
            cv.hh[3] = __floats2half2_rn(c[6], c[7]);
            *(float4*)&g_support16[(size_t)r * 256 + cg] = cv.f;
            float p1 = 0.f, p2 = 0.f;
#pragma unroll
            for (int j = 0; j < 8; j++) {
                p1 = fmaf(c[j], w1[j], p1);
                p2 = fmaf(c[j], w2[j], p2);
            }
            // reduce across the 8 lanes of this head group (lane bits 0..2)
#pragma unroll
            for (int o = 4; o >= 1; o >>= 1) {
                p1 += __shfl_xor_sync(0xffffffffu, p1, o);
                p2 += __shfl_xor_sync(0xffffffffu, p2, o);
            }
            if ((tx & 7) == 0) {
                g_f1[r * 4 + h] = p1;
                g_f2[r * 4 + h] = p2;
                mloc = fmaxf(mloc, p1);
            }
        }
        if ((tx & 7) == 0) atomicMax(&g_gmax_u[h], f_enc(mloc));
    }
}

// ---------------------------------------------------------------------------
// Per-node exp factorization (see round-3 comments): 65K exps total, zero in
// the hot loop. All factors <= 1 (shift by per-head global max); self loop
// guarantees a nonzero denominator.
// ---------------------------------------------------------------------------
__global__ __launch_bounds__(256) void precompute_kernel()
{
    const int n = blockIdx.x * 256 + threadIdx.x;
    float4 f1 = *(const float4*)&g_f1[n * 4];
    float4 f2 = *(const float4*)&g_f2[n * 4];
    const float f1a[4] = {f1.x, f1.y, f1.z, f1.w};
    const float f2a[4] = {f2.x, f2.y, f2.z, f2.w};
#pragma unroll
    for (int h = 0; h < NHEAD; h++) {
        float g = f_dec(g_gmax_u[h]);
        float d = f1a[h] - g;
        g_E1[n * 8 + h * 2 + 0] = __expf(d);
        g_E1[n * 8 + h * 2 + 1] = __expf(0.2f * d);
        float l = g + f2a[h];
        float M = fmaxf(l, 0.2f * l);
        float4 rc;
        rc.x = __expf(l - M);          // F2p
        rc.y = __expf(0.2f * l - M);   // F2n
        rc.z = __expf(-l);             // T: branch test E1p >= T  <=>  l_edge >= 0
        rc.w = 0.f;
        *(float4*)&g_rowc[n * 16 + h * 4] = rc;
    }
}

// ---------------------------------------------------------------------------
// L1-blocked aggregation. Grid 147 CTAs x 512 threads (16 warps), ~1 CTA/SM.
// CTA owns 56 rows (warp w: local rows w, w+16, w+32, w+48). m-dimension is
// processed in 256-row blocks (128KB fp16 support slice + 8KB E1 slice stays
// L1-resident; zero SMEM so full L1 carveout). __syncthreads between blocks
// keeps all warps on the same block. Per (row, block): 1KB adj scan (__ldcs,
// evict-first) -> 8 ballot words; gather iterates set bits directly (column
// recovered from bit index — no SMEM staging, no caps, no atomics). Each lane
// computes its own head's e from a broadcast 8B E1 read.
// ---------------------------------------------------------------------------
#define AG_ROWS  56
#define AG_WARPS 16
#define MB       256

__global__ __launch_bounds__(512) void aggregate_kernel(
    const float* __restrict__ adj, float* __restrict__ out)
{
    const int warp = threadIdx.x >> 5;
    const int lane = threadIdx.x & 31;
    const int h = lane >> 3;
    const int base = blockIdx.x * AG_ROWS;

    int rows[4]; int nrow = 0;
#pragma unroll
    for (int i = 0; i < 4; i++) {
        int lr = warp + i * AG_WARPS;
        int n = base + lr;
        rows[i] = n;
        if (lr < AG_ROWS && n < NROWS) nrow = i + 1;
    }

    float acc[4][8];
    float denom[4] = {0.f, 0.f, 0.f, 0.f};
#pragma unroll
    for (int i = 0; i < 4; i++)
#pragma unroll
        for (int j = 0; j < 8; j++) acc[i][j] = 0.f;

    const char* supb = (const char*)g_support16 + h * 128 + (lane & 7) * 16;

    for (int b = 0; b < NROWS / MB; b++) {
#pragma unroll
        for (int ri = 0; ri < 4; ri++) {
            if (ri >= nrow) break;                    // warp-uniform
            const int n = rows[ri];
            const float4 rc = *(const float4*)&g_rowc[n * 16 + h * 4];
            const float4* arow = (const float4*)(adj + (size_t)n * NROWS + b * MB);
            float4 a0 = __ldcs(&arow[lane]);
            float4 a1 = __ldcs(&arow[32 + lane]);
            unsigned bal[8];
            bal[0] = __ballot_sync(0xffffffffu, a0.x != 0.f);
            bal[1] = __ballot_sync(0xffffffffu, a0.y != 0.f);
            bal[2] = __ballot_sync(0xffffffffu, a0.z != 0.f);
            bal[3] = __ballot_sync(0xffffffffu, a0.w != 0.f);
            bal[4] = __ballot_sync(0xffffffffu, a1.x != 0.f);
            bal[5] = __ballot_sync(0xffffffffu, a1.y != 0.f);
            bal[6] = __ballot_sync(0xffffffffu, a1.z != 0.f);
            bal[7] = __ballot_sync(0xffffffffu, a1.w != 0.f);
#pragma unroll
            for (int k8 = 0; k8 < 8; k8++) {
                unsigned bw = bal[k8];
                const int cb = b * MB + ((k8 >> 2) << 7) + (k8 & 3);
                while (bw) {
                    int bi = __ffs(bw) - 1;
                    bw &= bw - 1;
                    int m = cb + bi * 4;
                    float2 e1 = *(const float2*)&g_E1[m * 8 + h * 2];
                    float e = (e1.x >= rc.z) ? e1.x * rc.x : e1.y * rc.y;
                    float4 raw = *(const float4*)(supb + ((size_t)m << 9));
                    const __half2* hp = (const __half2*)&raw;
                    float2 v0 = __half22float2(hp[0]);
                    float2 v1 = __half22float2(hp[1]);
                    float2 v2 = __half22float2(hp[2]);
                    float2 v3 = __half22float2(hp[3]);
                    acc[ri][0] = fmaf(e, v0.x, acc[ri][0]);
                    acc[ri][1] = fmaf(e, v0.y, acc[ri][1]);
                    acc[ri][2] = fmaf(e, v1.x, acc[ri][2]);
                    acc[ri][3] = fmaf(e, v1.y, acc[ri][3]);
                    acc[ri][4] = fmaf(e, v2.x, acc[ri][4]);
                    acc[ri][5] = fmaf(e, v2.y, acc[ri][5]);
                    acc[ri][6] = fmaf(e, v3.x, acc[ri][6]);
                    acc[ri][7] = fmaf(e, v3.y, acc[ri][7]);
                    denom[ri] += e;
                }
            }
        }
        __syncthreads();   // keep all warps on the same L1-resident block
    }

#pragma unroll
    for (int ri = 0; ri < 4; ri++) {
        if (ri >= nrow) break;
        const int n = rows[ri];
        const float inv = 1.0f / fmaxf(denom[ri], 1e-30f);
        float* orow = out + (size_t)n * 256 + h * 64 + (lane & 7) * 8;
        float4 o0 = *(float4*)orow;
        float4 o1 = *(float4*)(orow + 4);
        o0.x += acc[ri][0] * inv; o0.y += acc[ri][1] * inv;
        o0.z += acc[ri][2] * inv; o0.w += acc[ri][3] * inv;
        o1.x += acc[ri][4] * inv; o1.y += acc[ri][5] * inv;
        o1.z += acc[ri][6] * inv; o1.w += acc[ri][7] * inv;
        *(float4*)orow = o0;
        *(float4*)(orow + 4) = o1;
    }
}

// ---------------------------------------------------------------------------
extern "C" void kernel_launch(void* const* d_in, const int* in_sizes, int n_in,
                              void* d_out, int out_size)
{
    const float* inputs = (const float*)d_in[0];
    const float* adj    = (const float*)d_in[1];
    const float* weight = (const float*)d_in[2];
    const float* wu     = (const float*)d_in[3];
    const float* wv     = (const float*)d_in[4];
    const float* bias   = (const float*)d_in[5];
    const float* projw  = (const float*)d_in[6];
    const float* projb  = (const float*)d_in[7];
    float* out = (float*)d_out;

    init_kernel<<<1, 32>>>();

    dim3 grid_gemm(2, 128);
    gemm_kernel<0><<<grid_gemm, 256>>>(inputs, weight, nullptr, nullptr, wu, wv, nullptr);
    gemm_kernel<1><<<grid_gemm, 256>>>(inputs, projw, projb, bias, nullptr, nullptr, out);
    precompute_kernel<<<NROWS / 256, 256>>>();

    const int agrid = (NROWS + AG_ROWS - 1) / AG_ROWS;   // 147
    aggregate_kernel<<<agrid, 512>>>(adj, out);
}

// round 6
// speedup vs baseline: 1.4146x; 1.4146x over previous
#include <cuda_runtime.h>
#include <cuda_fp16.h>

#define NROWS 8192
#define NHEAD 4

// scratch (static device globals; no allocation in kernel_launch)
__device__ __half     g_support16[NROWS * 256];   // 4 MB, [n][h*64+o] fp16
__device__ float      g_f1[NROWS * NHEAD];        // [n][h]
__device__ float      g_f2[NROWS * NHEAD];        // [n][h]
__device__ unsigned   g_gmax_u[NHEAD];            // ordered-uint per-head max f1
__device__ float      g_E1[NROWS * 8];            // [m][h][{E1p,E1n}]
__device__ float      g_rowc[NROWS * 16];         // [n][h][{F2p,F2n,T,pad}]

__device__ __forceinline__ unsigned f_enc(float f) {
    unsigned b = __float_as_uint(f);
    return (b & 0x80000000u) ? ~b : (b | 0x80000000u);
}
__device__ __forceinline__ float f_dec(unsigned u) {
    return __uint_as_float((u & 0x80000000u) ? (u & 0x7FFFFFFFu) : ~u);
}

__global__ void init_kernel() {
    if (threadIdx.x < NHEAD) g_gmax_u[threadIdx.x] = 0u;
}

// ---- packed fp32x2 helpers (Blackwell FFMA2 via PTX) ----------------------
__device__ __forceinline__ void ffma2(unsigned long long& d,
                                      unsigned long long a, unsigned long long b) {
    asm("fma.rn.f32x2 %0, %1, %2, %0;" : "+l"(d) : "l"(a), "l"(b));
}
__device__ __forceinline__ unsigned long long pack2(float x) {
    unsigned long long r; unsigned u = __float_as_uint(x);
    asm("mov.b64 %0, {%1, %1};" : "=l"(r) : "r"(u));
    return r;
}
__device__ __forceinline__ float2 unpack2(unsigned long long v) {
    unsigned a, b;
    asm("mov.b64 {%0, %1}, %2;" : "=r"(a), "=r"(b) : "l"(v));
    return make_float2(__uint_as_float(a), __uint_as_float(b));
}

// ---------------------------------------------------------------------------
// GEMM: C[8192,256] = A[8192,256] @ op(B)[256,256], 64x128 tiles, 256 thr.
// Thread: 4 rows x 8 cols as 4 f32x2 pairs; math via fma.rn.f32x2.
//   TRANSB=0: op(B)=B. Epilogue: fp16 support, f1/f2 via 8-lane shfl, gmax.
//   TRANSB=1: op(B)=B^T. Writes C + bias1 + bias2 (residual base).
// ---------------------------------------------------------------------------
template <int TRANSB>
__global__ __launch_bounds__(256) void gemm_kernel(
    const float* __restrict__ A, const float* __restrict__ B,
    const float* __restrict__ bias1, const float* __restrict__ bias2,
    const float* __restrict__ wu, const float* __restrict__ wv,
    float* __restrict__ C)
{
    __shared__ __align__(16) float As[64][17];
    __shared__ __align__(16) float Bs[16][132];
    const int tid = threadIdx.x;
    const int r0 = blockIdx.y * 64;
    const int c0 = blockIdx.x * 128;
    const int tx = tid & 15, ty = tid >> 4;

    unsigned long long acc2[4][4];
#pragma unroll
    for (int i = 0; i < 4; i++)
#pragma unroll
        for (int j = 0; j < 4; j++) acc2[i][j] = 0ull;

    for (int kk = 0; kk < 256; kk += 16) {
#pragma unroll
        for (int i = 0; i < 4; i++) {
            int e = tid + i * 256;
            As[e >> 4][e & 15] = A[(size_t)(r0 + (e >> 4)) * 256 + kk + (e & 15)];
        }
#pragma unroll
        for (int i = 0; i < 8; i++) {
            int e = tid + i * 256;
            if (TRANSB) {
                int c = e >> 4, k = e & 15;
                Bs[k][c] = B[(size_t)(c0 + c) * 256 + kk + k];
            } else {
                int k = e >> 7, c = e & 127;
                Bs[k][c] = B[(size_t)(kk + k) * 256 + c0 + c];
            }
        }
        __syncthreads();
#pragma unroll
        for (int k = 0; k < 16; k++) {
            const ulonglong2* bp = (const ulonglong2*)&Bs[k][tx * 8];
            ulonglong2 bA = bp[0], bB = bp[1];
#pragma unroll
            for (int i = 0; i < 4; i++) {
                unsigned long long a2 = pack2(As[ty * 4 + i][k]);
                ffma2(acc2[i][0], a2, bA.x);
                ffma2(acc2[i][1], a2, bA.y);
                ffma2(acc2[i][2], a2, bB.x);
                ffma2(acc2[i][3], a2, bB.y);
            }
        }
        __syncthreads();
    }

    const int cg = c0 + tx * 8;
    if (TRANSB) {
        float bsum[8];
#pragma unroll
        for (int j = 0; j < 8; j++) bsum[j] = bias1[cg + j] + bias2[cg + j];
#pragma unroll
        for (int i = 0; i < 4; i++) {
            int r = r0 + ty * 4 + i;
            float2 p0 = unpack2(acc2[i][0]), p1 = unpack2(acc2[i][1]);
            float2 p2 = unpack2(acc2[i][2]), p3 = unpack2(acc2[i][3]);
            float4 o0 = make_float4(p0.x + bsum[0], p0.y + bsum[1],
                                    p1.x + bsum[2], p1.y + bsum[3]);
            float4 o1 = make_float4(p2.x + bsum[4], p2.y + bsum[5],
                                    p3.x + bsum[6], p3.y + bsum[7]);
            *(float4*)&C[(size_t)r * 256 + cg] = o0;
            *(float4*)&C[(size_t)r * 256 + cg + 4] = o1;
        }
    } else {
        const int h = blockIdx.x * 2 + (tx >> 3);
        float w1[8], w2[8];
#pragma unroll
        for (int j = 0; j < 8; j++) { w1[j] = wu[cg + j]; w2[j] = wv[cg + j]; }
        float mloc = -3.0e38f;
#pragma unroll
        for (int i = 0; i < 4; i++) {
            int r = r0 + ty * 4 + i;
            float c[8];
            float2 q;
            q = unpack2(acc2[i][0]); c[0] = q.x; c[1] = q.y;
            q = unpack2(acc2[i][1]); c[2] = q.x; c[3] = q.y;
            q = unpack2(acc2[i][2]); c[4] = q.x; c[5] = q.y;
            q = unpack2(acc2[i][3]); c[6] = q.x; c[7] = q.y;
            union { __half2 hh[4]; float4 f; } cv;
            cv.hh[0] = __floats2half2_rn(c[0], c[1]);
            cv.hh[1] = __floats2half2_rn(c[2], c[3]);
            cv.hh[2] = __floats2half2_rn(c[4], c[5]);
            cv.hh[3] = __floats2half2_rn(c[6], c[7]);
            *(float4*)&g_support16[(size_t)r * 256 + cg] = cv.f;
            float p1 = 0.f, p2 = 0.f;
#pragma unroll
            for (int j = 0; j < 8; j++) {
                p1 = fmaf(c[j], w1[j], p1);
                p2 = fmaf(c[j], w2[j], p2);
            }
            // reduce across the 8 lanes of this head group (lane bits 0..2)
#pragma unroll
            for (int o = 4; o >= 1; o >>= 1) {
                p1 += __shfl_xor_sync(0xffffffffu, p1, o);
                p2 += __shfl_xor_sync(0xffffffffu, p2, o);
            }
            if ((tx & 7) == 0) {
                g_f1[r * 4 + h] = p1;
                g_f2[r * 4 + h] = p2;
                mloc = fmaxf(mloc, p1);
            }
        }
        if ((tx & 7) == 0) atomicMax(&g_gmax_u[h], f_enc(mloc));
    }
}

// ---------------------------------------------------------------------------
// Per-node exp factorization: 65K exps total, zero in the hot loop.
//   e(n,m,h) = l>=0 ? E1p[m]*F2p[n] : E1n[m]*F2n[n],  l = f1[m]+f2[n]
//   branch test: E1p[m] >= T[n] = exp(-f2-g). All factors <= 1 (shift by
//   per-head global max); self loop guarantees nonzero denominator.
// ---------------------------------------------------------------------------
__global__ __launch_bounds__(256) void precompute_kernel()
{
    const int n = blockIdx.x * 256 + threadIdx.x;
    float4 f1 = *(const float4*)&g_f1[n * 4];
    float4 f2 = *(const float4*)&g_f2[n * 4];
    const float f1a[4] = {f1.x, f1.y, f1.z, f1.w};
    const float f2a[4] = {f2.x, f2.y, f2.z, f2.w};
#pragma unroll
    for (int h = 0; h < NHEAD; h++) {
        float g = f_dec(g_gmax_u[h]);
        float d = f1a[h] - g;
        g_E1[n * 8 + h * 2 + 0] = __expf(d);
        g_E1[n * 8 + h * 2 + 1] = __expf(0.2f * d);
        float l = g + f2a[h];
        float M = fmaxf(l, 0.2f * l);
        float4 rc;
        rc.x = __expf(l - M);          // F2p
        rc.y = __expf(0.2f * l - M);   // F2n
        rc.z = __expf(-l);             // T
        rc.w = 0.f;
        *(float4*)&g_rowc[n * 16 + h * 4] = rc;
    }
}

// ---------------------------------------------------------------------------
// Aggregation (round-4 structure — the 307.9us version, reverted verbatim):
// one WARP per row n (4 warps/CTA, grid 2048, no CTA barriers). Lane owns
// 8 cols (head h = lane>>3, LDG.128 fp16). Per 2048-col chunk: ballot/popc
// compaction into s_m; e-phase packs {byte-offset, e} int2 per (edge, head);
// gather loop 8-unrolled (independent LDS+LDG, high MLP).
// ---------------------------------------------------------------------------
#define CCAP 192   // max edges per 2048-col chunk (mean 102, sd ~10)

__global__ __launch_bounds__(128) void aggregate_kernel(
    const float* __restrict__ adj, float* __restrict__ out)
{
    __shared__ int  s_m[4][CCAP];
    __shared__ int2 s_em[4][CCAP * 4];

    const int warp = threadIdx.x >> 5;
    const int lane = threadIdx.x & 31;
    const int n = blockIdx.x * 4 + warp;
    const int h = lane >> 3;

    float F2p[4], F2n[4], Tt[4];
#pragma unroll
    for (int hh = 0; hh < 4; hh++) {
        float4 rc = *(const float4*)&g_rowc[n * 16 + hh * 4];
        F2p[hh] = rc.x; F2n[hh] = rc.y; Tt[hh] = rc.z;
    }

    const char* supb = (const char*)g_support16 + h * 128 + (lane & 7) * 16;
    float ax0 = 0.f, ay0 = 0.f, ax1 = 0.f, ay1 = 0.f;
    float ax2 = 0.f, ay2 = 0.f, ax3 = 0.f, ay3 = 0.f;
    float denom = 0.f;

    const float4* arow = reinterpret_cast<const float4*>(adj + (size_t)n * NROWS);
    const unsigned lt = (1u << lane) - 1u;

    for (int c0 = 0; c0 < NROWS; c0 += 2048) {
        int cnt = 0;
        // ---- scan + warp compaction (order-free; sum is commutative) ----
#pragma unroll 4
        for (int j = 0; j < 16; j++) {
            float4 a4 = __ldcs(&arow[(c0 >> 2) + j * 32 + lane]);
            int col = c0 + (j * 32 + lane) * 4;
            unsigned b;
            b = __ballot_sync(0xffffffffu, a4.x != 0.f);
            if (a4.x != 0.f) { int p = cnt + __popc(b & lt); if (p < CCAP) s_m[warp][p] = col; }
            cnt += __popc(b);
            b = __ballot_sync(0xffffffffu, a4.y != 0.f);
            if (a4.y != 0.f) { int p = cnt + __popc(b & lt); if (p < CCAP) s_m[warp][p] = col + 1; }
            cnt += __popc(b);
            b = __ballot_sync(0xffffffffu, a4.z != 0.f);
            if (a4.z != 0.f) { int p = cnt + __popc(b & lt); if (p < CCAP) s_m[warp][p] = col + 2; }
            cnt += __popc(b);
            b = __ballot_sync(0xffffffffu, a4.w != 0.f);
            if (a4.w != 0.f) { int p = cnt + __popc(b & lt); if (p < CCAP) s_m[warp][p] = col + 3; }
            cnt += __popc(b);
        }
        cnt = min(cnt, CCAP);
        __syncwarp();

        // ---- e-phase: no exp, compare-select-mul per head ----
        for (int i = lane; i < cnt; i += 32) {
            int m = s_m[warp][i];
            float4 ea = *(const float4*)&g_E1[m * 8];       // h0:{p,n} h1:{p,n}
            float4 eb = *(const float4*)&g_E1[m * 8 + 4];   // h2:{p,n} h3:{p,n}
            int moff = m << 9;                              // m * 512 bytes
            float e0 = (ea.x >= Tt[0]) ? ea.x * F2p[0] : ea.y * F2n[0];
            float e1 = (ea.z >= Tt[1]) ? ea.z * F2p[1] : ea.w * F2n[1];
            float e2 = (eb.x >= Tt[2]) ? eb.x * F2p[2] : eb.y * F2n[2];
            float e3 = (eb.z >= Tt[3]) ? eb.z * F2p[3] : eb.w * F2n[3];
            s_em[warp][i * 4 + 0] = make_int2(moff, __float_as_int(e0));
            s_em[warp][i * 4 + 1] = make_int2(moff, __float_as_int(e1));
            s_em[warp][i * 4 + 2] = make_int2(moff, __float_as_int(e2));
            s_em[warp][i * 4 + 3] = make_int2(moff, __float_as_int(e3));
        }
        __syncwarp();

        // ---- gather + accumulate ----
        int i = 0;
        for (; i + 8 <= cnt; i += 8) {
#pragma unroll
            for (int u = 0; u < 8; u++) {
                int2 em = s_em[warp][(i + u) * 4 + h];
                float e = __int_as_float(em.y);
                float4 raw = *(const float4*)(supb + em.x);
                const __half2* hp = (const __half2*)&raw;
                float2 v0 = __half22float2(hp[0]);
                float2 v1 = __half22float2(hp[1]);
                float2 v2 = __half22float2(hp[2]);
                float2 v3 = __half22float2(hp[3]);
                ax0 = fmaf(e, v0.x, ax0); ay0 = fmaf(e, v0.y, ay0);
                ax1 = fmaf(e, v1.x, ax1); ay1 = fmaf(e, v1.y, ay1);
                ax2 = fmaf(e, v2.x, ax2); ay2 = fmaf(e, v2.y, ay2);
                ax3 = fmaf(e, v3.x, ax3); ay3 = fmaf(e, v3.y, ay3);
                denom += e;
            }
        }
        for (; i < cnt; i++) {
            int2 em = s_em[warp][i * 4 + h];
            float e = __int_as_float(em.y);
            float4 raw = *(const float4*)(supb + em.x);
            const __half2* hp = (const __half2*)&raw;
            float2 v0 = __half22float2(hp[0]);
            float2 v1 = __half22float2(hp[1]);
            float2 v2 = __half22float2(hp[2]);
            float2 v3 = __half22float2(hp[3]);
            ax0 = fmaf(e, v0.x, ax0); ay0 = fmaf(e, v0.y, ay0);
            ax1 = fmaf(e, v1.x, ax1); ay1 = fmaf(e, v1.y, ay1);
            ax2 = fmaf(e, v2.x, ax2); ay2 = fmaf(e, v2.y, ay2);
            ax3 = fmaf(e, v3.x, ax3); ay3 = fmaf(e, v3.y, ay3);
            denom += e;
        }
        __syncwarp();
    }

    const float inv = 1.0f / fmaxf(denom, 1e-30f);
    float* orow = out + (size_t)n * 256 + h * 64 + (lane & 7) * 8;
    float4 o0 = *(float4*)orow;
    float4 o1 = *(float4*)(orow + 4);
    o0.x += ax0 * inv; o0.y += ay0 * inv;
    o0.z += ax1 * inv; o0.w += ay1 * inv;
    o1.x += ax2 * inv; o1.y += ay2 * inv;
    o1.z += ax3 * inv; o1.w += ay3 * inv;
    *(float4*)orow = o0;
    *(float4*)(orow + 4) = o1;
}

// ---------------------------------------------------------------------------
extern "C" void kernel_launch(void* const* d_in, const int* in_sizes, int n_in,
                              void* d_out, int out_size)
{
    const float* inputs = (const float*)d_in[0];
    const float* adj    = (const float*)d_in[1];
    const float* weight = (const float*)d_in[2];
    const float* wu     = (const float*)d_in[3];
    const float* wv     = (const float*)d_in[4];
    const float* bias   = (const float*)d_in[5];
    const float* projw  = (const float*)d_in[6];
    const float* projb  = (const float*)d_in[7];
    float* out = (float*)d_out;

    init_kernel<<<1, 32>>>();

    dim3 grid_gemm(2, 128);
    gemm_kernel<0><<<grid_gemm, 256>>>(inputs, weight, nullptr, nullptr, wu, wv, nullptr);
    gemm_kernel<1><<<grid_gemm, 256>>>(inputs, projw, projb, bias, nullptr, nullptr, out);
    precompute_kernel<<<NROWS / 256, 256>>>();
    aggregate_kernel<<<NROWS / 4, 128>>>(adj, out);
}

// round 7
// speedup vs baseline: 1.5927x; 1.1259x over previous
#include <cuda_runtime.h>
#include <cuda_fp16.h>

#define NROWS 8192
#define NHEAD 4

// scratch (static device globals; no allocation in kernel_launch)
__device__ __half     g_support16[NROWS * 256];   // 4 MB, [n][h*64+o] fp16
__device__ float      g_f1[NROWS * NHEAD];        // [n][h]
__device__ float      g_f2[NROWS * NHEAD];        // [n][h]
__device__ unsigned   g_gmax_u[NHEAD];            // ordered-uint per-head max f1
__device__ float      g_E1[NROWS * 8];            // [m][h][{E1p,E1n}]
__device__ float      g_rowc[NROWS * 16];         // [n][h][{F2p,F2n,T,pad}]

__device__ __forceinline__ unsigned f_enc(float f) {
    unsigned b = __float_as_uint(f);
    return (b & 0x80000000u) ? ~b : (b | 0x80000000u);
}
__device__ __forceinline__ float f_dec(unsigned u) {
    return __uint_as_float((u & 0x80000000u) ? (u & 0x7FFFFFFFu) : ~u);
}

__global__ void init_kernel() {
    if (threadIdx.x < NHEAD) g_gmax_u[threadIdx.x] = 0u;
}

// ---------------------------------------------------------------------------
// Fused dual GEMM: 128x128 CTA tiles, 8x8 register tile per thread (256 thr),
// plain FFMA (the f32x2 experiment regressed; reverted).
//   z = blockIdx.z:
//     z=0: C = A @ weight          -> fp16 support + f1/f2 + per-head gmax
//     z=1: C = A @ projw^T + biases -> residual base into out
// A staged transposed in SMEM (As[k][r], pad 132) so mainloop reads are
// LDS.128 conflict-free; 64 FFMA per 4 LDS.128 per k-step (~90% FMA-bound).
// ---------------------------------------------------------------------------
__global__ __launch_bounds__(256) void gemm_fused(
    const float* __restrict__ A, const float* __restrict__ Bw,
    const float* __restrict__ Bp, const float* __restrict__ projb,
    const float* __restrict__ bias,
    const float* __restrict__ wu, const float* __restrict__ wv,
    float* __restrict__ out)
{
    __shared__ __align__(16) float As[16][132];
    __shared__ __align__(16) float Bs[16][132];
    const int tid = threadIdx.x;
    const int z = blockIdx.z;
    const int r0 = blockIdx.y * 128;
    const int c0 = blockIdx.x * 128;
    const int tx = tid & 15, ty = tid >> 4;
    const float* __restrict__ B = z ? Bp : Bw;

    float acc[8][8];
#pragma unroll
    for (int i = 0; i < 8; i++)
#pragma unroll
        for (int j = 0; j < 8; j++) acc[i][j] = 0.f;

    for (int kk = 0; kk < 256; kk += 16) {
        // A tile, transposed store: As[k][r] = A[r0+r][kk+k]
#pragma unroll
        for (int i = 0; i < 2; i++) {
            int p = tid + i * 256;
            int r = p >> 2, q = (p & 3) * 4;
            float4 v = *(const float4*)&A[(size_t)(r0 + r) * 256 + kk + q];
            As[q + 0][r] = v.x; As[q + 1][r] = v.y;
            As[q + 2][r] = v.z; As[q + 3][r] = v.w;
        }
        // B tile
        if (z == 0) {
#pragma unroll
            for (int i = 0; i < 2; i++) {
                int p = tid + i * 256;
                int k = p >> 5, c = (p & 31) * 4;
                *(float4*)&Bs[k][c] = *(const float4*)&B[(size_t)(kk + k) * 256 + c0 + c];
            }
        } else {
#pragma unroll
            for (int i = 0; i < 2; i++) {
                int p = tid + i * 256;
                int c = p >> 2, q = (p & 3) * 4;
                float4 v = *(const float4*)&B[(size_t)(c0 + c) * 256 + kk + q];
                Bs[q + 0][c] = v.x; Bs[q + 1][c] = v.y;
                Bs[q + 2][c] = v.z; Bs[q + 3][c] = v.w;
            }
        }
        __syncthreads();
#pragma unroll
        for (int k = 0; k < 16; k++) {
            float4 a0 = *(const float4*)&As[k][ty * 8];
            float4 a1 = *(const float4*)&As[k][ty * 8 + 4];
            float4 b0 = *(const float4*)&Bs[k][tx * 8];
            float4 b1 = *(const float4*)&Bs[k][tx * 8 + 4];
            const float av[8] = {a0.x, a0.y, a0.z, a0.w, a1.x, a1.y, a1.z, a1.w};
            const float bv[8] = {b0.x, b0.y, b0.z, b0.w, b1.x, b1.y, b1.z, b1.w};
#pragma unroll
            for (int i = 0; i < 8; i++)
#pragma unroll
                for (int j = 0; j < 8; j++)
                    acc[i][j] = fmaf(av[i], bv[j], acc[i][j]);
        }
        __syncthreads();
    }

    const int cg = c0 + tx * 8;
    if (z == 1) {
        float bsum[8];
#pragma unroll
        for (int j = 0; j < 8; j++) bsum[j] = projb[cg + j] + bias[cg + j];
#pragma unroll
        for (int i = 0; i < 8; i++) {
            int r = r0 + ty * 8 + i;
            float4 o0 = make_float4(acc[i][0] + bsum[0], acc[i][1] + bsum[1],
                                    acc[i][2] + bsum[2], acc[i][3] + bsum[3]);
            float4 o1 = make_float4(acc[i][4] + bsum[4], acc[i][5] + bsum[5],
                                    acc[i][6] + bsum[6], acc[i][7] + bsum[7]);
            *(float4*)&out[(size_t)r * 256 + cg] = o0;
            *(float4*)&out[(size_t)r * 256 + cg + 4] = o1;
        }
    } else {
        const int h = blockIdx.x * 2 + (tx >> 3);
        float w1[8], w2[8];
#pragma unroll
        for (int j = 0; j < 8; j++) { w1[j] = wu[cg + j]; w2[j] = wv[cg + j]; }
        float mloc = -3.0e38f;
#pragma unroll
        for (int i = 0; i < 8; i++) {
            int r = r0 + ty * 8 + i;
            union { __half2 hh[4]; float4 f; } cv;
            cv.hh[0] = __floats2half2_rn(acc[i][0], acc[i][1]);
            cv.hh[1] = __floats2half2_rn(acc[i][2], acc[i][3]);
            cv.hh[2] = __floats2half2_rn(acc[i][4], acc[i][5]);
            cv.hh[3] = __floats2half2_rn(acc[i][6], acc[i][7]);
            *(float4*)&g_support16[(size_t)r * 256 + cg] = cv.f;
            float p1 = 0.f, p2 = 0.f;
#pragma unroll
            for (int j = 0; j < 8; j++) {
                p1 = fmaf(acc[i][j], w1[j], p1);
                p2 = fmaf(acc[i][j], w2[j], p2);
            }
            // reduce across the 8 tx-lanes of this head group (lane bits 0..2)
#pragma unroll
            for (int o = 4; o >= 1; o >>= 1) {
                p1 += __shfl_xor_sync(0xffffffffu, p1, o);
                p2 += __shfl_xor_sync(0xffffffffu, p2, o);
            }
            if ((tx & 7) == 0) {
                g_f1[r * 4 + h] = p1;
                g_f2[r * 4 + h] = p2;
                mloc = fmaxf(mloc, p1);
            }
        }
        if ((tx & 7) == 0) atomicMax(&g_gmax_u[h], f_enc(mloc));
    }
}

// ---------------------------------------------------------------------------
// Per-node exp factorization: 65K exps total, zero in the hot loop.
//   e(n,m,h) = l>=0 ? E1p[m]*F2p[n] : E1n[m]*F2n[n],  l = f1[m]+f2[n]
//   branch test: E1p[m] >= T[n] = exp(-f2-g). All factors <= 1 (shift by
//   per-head global max); self loop guarantees nonzero denominator.
// ---------------------------------------------------------------------------
__global__ __launch_bounds__(256) void precompute_kernel()
{
    const int n = blockIdx.x * 256 + threadIdx.x;
    float4 f1 = *(const float4*)&g_f1[n * 4];
    float4 f2 = *(const float4*)&g_f2[n * 4];
    const float f1a[4] = {f1.x, f1.y, f1.z, f1.w};
    const float f2a[4] = {f2.x, f2.y, f2.z, f2.w};
#pragma unroll
    for (int h = 0; h < NHEAD; h++) {
        float g = f_dec(g_gmax_u[h]);
        float d = f1a[h] - g;
        g_E1[n * 8 + h * 2 + 0] = __expf(d);
        g_E1[n * 8 + h * 2 + 1] = __expf(0.2f * d);
        float l = g + f2a[h];
        float M = fmaxf(l, 0.2f * l);
        float4 rc;
        rc.x = __expf(l - M);          // F2p
        rc.y = __expf(0.2f * l - M);   // F2n
        rc.z = __expf(-l);             // T
        rc.w = 0.f;
        *(float4*)&g_rowc[n * 16 + h * 4] = rc;
    }
}

// ---------------------------------------------------------------------------
// Aggregation (round-4 structure, the proven 307.9us version, unchanged):
// one WARP per row n (4 warps/CTA, grid 2048, no CTA barriers). Lane owns
// 8 cols (head h = lane>>3, LDG.128 fp16). Per 2048-col chunk: ballot/popc
// compaction into s_m; e-phase packs {byte-offset, e} int2 per (edge, head);
// gather loop 8-unrolled (independent LDS+LDG, high MLP).
// ---------------------------------------------------------------------------
#define CCAP 192   // max edges per 2048-col chunk (mean 102, sd ~10)

__global__ __launch_bounds__(128) void aggregate_kernel(
    const float* __restrict__ adj, float* __restrict__ out)
{
    __shared__ int  s_m[4][CCAP];
    __shared__ int2 s_em[4][CCAP * 4];

    const int warp = threadIdx.x >> 5;
    const int lane = threadIdx.x & 31;
    const int n = blockIdx.x * 4 + warp;
    const int h = lane >> 3;

    float F2p[4], F2n[4], Tt[4];
#pragma unroll
    for (int hh = 0; hh < 4; hh++) {
        float4 rc = *(const float4*)&g_rowc[n * 16 + hh * 4];
        F2p[hh] = rc.x; F2n[hh] = rc.y; Tt[hh] = rc.z;
    }

    const char* supb = (const char*)g_support16 + h * 128 + (lane & 7) * 16;
    float ax0 = 0.f, ay0 = 0.f, ax1 = 0.f, ay1 = 0.f;
    float ax2 = 0.f, ay2 = 0.f, ax3 = 0.f, ay3 = 0.f;
    float denom = 0.f;

    const float4* arow = reinterpret_cast<const float4*>(adj + (size_t)n * NROWS);
    const unsigned lt = (1u << lane) - 1u;

    for (int c0 = 0; c0 < NROWS; c0 += 2048) {
        int cnt = 0;
        // ---- scan + warp compaction (order-free; sum is commutative) ----
#pragma unroll 4
        for (int j = 0; j < 16; j++) {
            float4 a4 = __ldcs(&arow[(c0 >> 2) + j * 32 + lane]);
            int col = c0 + (j * 32 + lane) * 4;
            unsigned b;
            b = __ballot_sync(0xffffffffu, a4.x != 0.f);
            if (a4.x != 0.f) { int p = cnt + __popc(b & lt); if (p < CCAP) s_m[warp][p] = col; }
            cnt += __popc(b);
            b = __ballot_sync(0xffffffffu, a4.y != 0.f);
            if (a4.y != 0.f) { int p = cnt + __popc(b & lt); if (p < CCAP) s_m[warp][p] = col + 1; }
            cnt += __popc(b);
            b = __ballot_sync(0xffffffffu, a4.z != 0.f);
            if (a4.z != 0.f) { int p = cnt + __popc(b & lt); if (p < CCAP) s_m[warp][p] = col + 2; }
            cnt += __popc(b);
            b = __ballot_sync(0xffffffffu, a4.w != 0.f);
            if (a4.w != 0.f) { int p = cnt + __popc(b & lt); if (p < CCAP) s_m[warp][p] = col + 3; }
            cnt += __popc(b);
        }
        cnt = min(cnt, CCAP);
        __syncwarp();

        // ---- e-phase: no exp, compare-select-mul per head ----
        for (int i = lane; i < cnt; i += 32) {
            int m = s_m[warp][i];
            float4 ea = *(const float4*)&g_E1[m * 8];       // h0:{p,n} h1:{p,n}
            float4 eb = *(const float4*)&g_E1[m * 8 + 4];   // h2:{p,n} h3:{p,n}
            int moff = m << 9;                              // m * 512 bytes
            float e0 = (ea.x >= Tt[0]) ? ea.x * F2p[0] : ea.y * F2n[0];
            float e1 = (ea.z >= Tt[1]) ? ea.z * F2p[1] : ea.w * F2n[1];
            float e2 = (eb.x >= Tt[2]) ? eb.x * F2p[2] : eb.y * F2n[2];
            float e3 = (eb.z >= Tt[3]) ? eb.z * F2p[3] : eb.w * F2n[3];
            s_em[warp][i * 4 + 0] = make_int2(moff, __float_as_int(e0));
            s_em[warp][i * 4 + 1] = make_int2(moff, __float_as_int(e1));
            s_em[warp][i * 4 + 2] = make_int2(moff, __float_as_int(e2));
            s_em[warp][i * 4 + 3] = make_int2(moff, __float_as_int(e3));
        }
        __syncwarp();

        // ---- gather + accumulate ----
        int i = 0;
        for (; i + 8 <= cnt; i += 8) {
#pragma unroll
            for (int u = 0; u < 8; u++) {
                int2 em = s_em[warp][(i + u) * 4 + h];
                float e = __int_as_float(em.y);
                float4 raw = *(const float4*)(supb + em.x);
                const __half2* hp = (const __half2*)&raw;
                float2 v0 = __half22float2(hp[0]);
                float2 v1 = __half22float2(hp[1]);
                float2 v2 = __half22float2(hp[2]);
                float2 v3 = __half22float2(hp[3]);
                ax0 = fmaf(e, v0.x, ax0); ay0 = fmaf(e, v0.y, ay0);
                ax1 = fmaf(e, v1.x, ax1); ay1 = fmaf(e, v1.y, ay1);
                ax2 = fmaf(e, v2.x, ax2); ay2 = fmaf(e, v2.y, ay2);
                ax3 = fmaf(e, v3.x, ax3); ay3 = fmaf(e, v3.y, ay3);
                denom += e;
            }
        }
        for (; i < cnt; i++) {
            int2 em = s_em[warp][i * 4 + h];
            float e = __int_as_float(em.y);
            float4 raw = *(const float4*)(supb + em.x);
            const __half2* hp = (const __half2*)&raw;
            float2 v0 = __half22float2(hp[0]);
            float2 v1 = __half22float2(hp[1]);
            float2 v2 = __half22float2(hp[2]);
            float2 v3 = __half22float2(hp[3]);
            ax0 = fmaf(e, v0.x, ax0); ay0 = fmaf(e, v0.y, ay0);
            ax1 = fmaf(e, v1.x, ax1); ay1 = fmaf(e, v1.y, ay1);
            ax2 = fmaf(e, v2.x, ax2); ay2 = fmaf(e, v2.y, ay2);
            ax3 = fmaf(e, v3.x, ax3); ay3 = fmaf(e, v3.y, ay3);
            denom += e;
        }
        __syncwarp();
    }

    const float inv = 1.0f / fmaxf(denom, 1e-30f);
    float* orow = out + (size_t)n * 256 + h * 64 + (lane & 7) * 8;
    float4 o0 = *(float4*)orow;
    float4 o1 = *(float4*)(orow + 4);
    o0.x += ax0 * inv; o0.y += ay0 * inv;
    o0.z += ax1 * inv; o0.w += ay1 * inv;
    o1.x += ax2 * inv; o1.y += ay2 * inv;
    o1.z += ax3 * inv; o1.w += ay3 * inv;
    *(float4*)orow = o0;
    *(float4*)(orow + 4) = o1;
}

// ---------------------------------------------------------------------------
extern "C" void kernel_launch(void* const* d_in, const int* in_sizes, int n_in,
                              void* d_out, int out_size)
{
    const float* inputs = (const float*)d_in[0];
    const float* adj    = (const float*)d_in[1];
    const float* weight = (const float*)d_in[2];
    const float* wu     = (const float*)d_in[3];
    const float* wv     = (const float*)d_in[4];
    const float* bias   = (const float*)d_in[5];
    const float* projw  = (const float*)d_in[6];
    const float* projb  = (const float*)d_in[7];
    float* out = (float*)d_out;

    init_kernel<<<1, 32>>>();

    dim3 grid_gemm(2, 64, 2);
    gemm_fused<<<grid_gemm, 256>>>(inputs, weight, projw, projb, bias, wu, wv, out);
    precompute_kernel<<<NROWS / 256, 256>>>();
    aggregate_kernel<<<NROWS / 4, 128>>>(adj, out);
}

// round 8
// speedup vs baseline: 1.8727x; 1.1758x over previous
#include <cuda_runtime.h>
#include <cuda_fp16.h>

#define NROWS 8192
#define NHEAD 4

// scratch (static device globals; no allocation in kernel_launch)
__device__ __half     g_support16[NROWS * 256];   // 4 MB, [n][h*64+o] fp16
__device__ float      g_f1[NROWS * NHEAD];        // [n][h]
__device__ float      g_f2[NROWS * NHEAD];        // [n][h]
__device__ unsigned   g_gmax_u[NHEAD];            // ordered-uint per-head max f1
__device__ float      g_E1[NROWS * 8];            // [m][h][{E1p,E1n}]
__device__ float      g_rowc[NROWS * 16];         // [n][h][{F2p,F2n,T,pad}]

__device__ __forceinline__ unsigned f_enc(float f) {
    unsigned b = __float_as_uint(f);
    return (b & 0x80000000u) ? ~b : (b | 0x80000000u);
}
__device__ __forceinline__ float f_dec(unsigned u) {
    return __uint_as_float((u & 0x80000000u) ? (u & 0x7FFFFFFFu) : ~u);
}

__global__ void init_kernel() {
    if (threadIdx.x < NHEAD) g_gmax_u[threadIdx.x] = 0u;
}

// ---------------------------------------------------------------------------
// Fused dual GEMM: 128x128 CTA tiles, 8x8 register tile per thread (256 thr).
//   z=0: C = A @ weight           -> fp16 support + f1/f2 + per-head gmax
//   z=1: C = A @ projw^T + biases -> residual base into out
// ---------------------------------------------------------------------------
__global__ __launch_bounds__(256) void gemm_fused(
    const float* __restrict__ A, const float* __restrict__ Bw,
    const float* __restrict__ Bp, const float* __restrict__ projb,
    const float* __restrict__ bias,
    const float* __restrict__ wu, const float* __restrict__ wv,
    float* __restrict__ out)
{
    __shared__ __align__(16) float As[16][132];
    __shared__ __align__(16) float Bs[16][132];
    const int tid = threadIdx.x;
    const int z = blockIdx.z;
    const int r0 = blockIdx.y * 128;
    const int c0 = blockIdx.x * 128;
    const int tx = tid & 15, ty = tid >> 4;
    const float* __restrict__ B = z ? Bp : Bw;

    float acc[8][8];
#pragma unroll
    for (int i = 0; i < 8; i++)
#pragma unroll
        for (int j = 0; j < 8; j++) acc[i][j] = 0.f;

    for (int kk = 0; kk < 256; kk += 16) {
#pragma unroll
        for (int i = 0; i < 2; i++) {
            int p = tid + i * 256;
            int r = p >> 2, q = (p & 3) * 4;
            float4 v = *(const float4*)&A[(size_t)(r0 + r) * 256 + kk + q];
            As[q + 0][r] = v.x; As[q + 1][r] = v.y;
            As[q + 2][r] = v.z; As[q + 3][r] = v.w;
        }
        if (z == 0) {
#pragma unroll
            for (int i = 0; i < 2; i++) {
                int p = tid + i * 256;
                int k = p >> 5, c = (p & 31) * 4;
                *(float4*)&Bs[k][c] = *(const float4*)&B[(size_t)(kk + k) * 256 + c0 + c];
            }
        } else {
#pragma unroll
            for (int i = 0; i < 2; i++) {
                int p = tid + i * 256;
                int c = p >> 2, q = (p & 3) * 4;
                float4 v = *(const float4*)&B[(size_t)(c0 + c) * 256 + kk + q];
                Bs[q + 0][c] = v.x; Bs[q + 1][c] = v.y;
                Bs[q + 2][c] = v.z; Bs[q + 3][c] = v.w;
            }
        }
        __syncthreads();
#pragma unroll
        for (int k = 0; k < 16; k++) {
            float4 a0 = *(const float4*)&As[k][ty * 8];
            float4 a1 = *(const float4*)&As[k][ty * 8 + 4];
            float4 b0 = *(const float4*)&Bs[k][tx * 8];
            float4 b1 = *(const float4*)&Bs[k][tx * 8 + 4];
            const float av[8] = {a0.x, a0.y, a0.z, a0.w, a1.x, a1.y, a1.z, a1.w};
            const float bv[8] = {b0.x, b0.y, b0.z, b0.w, b1.x, b1.y, b1.z, b1.w};
#pragma unroll
            for (int i = 0; i < 8; i++)
#pragma unroll
                for (int j = 0; j < 8; j++)
                    acc[i][j] = fmaf(av[i], bv[j], acc[i][j]);
        }
        __syncthreads();
    }

    const int cg = c0 + tx * 8;
    if (z == 1) {
        float bsum[8];
#pragma unroll
        for (int j = 0; j < 8; j++) bsum[j] = projb[cg + j] + bias[cg + j];
#pragma unroll
        for (int i = 0; i < 8; i++) {
            int r = r0 + ty * 8 + i;
            float4 o0 = make_float4(acc[i][0] + bsum[0], acc[i][1] + bsum[1],
                                    acc[i][2] + bsum[2], acc[i][3] + bsum[3]);
            float4 o1 = make_float4(acc[i][4] + bsum[4], acc[i][5] + bsum[5],
                                    acc[i][6] + bsum[6], acc[i][7] + bsum[7]);
            *(float4*)&out[(size_t)r * 256 + cg] = o0;
            *(float4*)&out[(size_t)r * 256 + cg + 4] = o1;
        }
    } else {
        const int h = blockIdx.x * 2 + (tx >> 3);
        float w1[8], w2[8];
#pragma unroll
        for (int j = 0; j < 8; j++) { w1[j] = wu[cg + j]; w2[j] = wv[cg + j]; }
        float mloc = -3.0e38f;
#pragma unroll
        for (int i = 0; i < 8; i++) {
            int r = r0 + ty * 8 + i;
            union { __half2 hh[4]; float4 f; } cv;
            cv.hh[0] = __floats2half2_rn(acc[i][0], acc[i][1]);
            cv.hh[1] = __floats2half2_rn(acc[i][2], acc[i][3]);
            cv.hh[2] = __floats2half2_rn(acc[i][4], acc[i][5]);
            cv.hh[3] = __floats2half2_rn(acc[i][6], acc[i][7]);
            *(float4*)&g_support16[(size_t)r * 256 + cg] = cv.f;
            float p1 = 0.f, p2 = 0.f;
#pragma unroll
            for (int j = 0; j < 8; j++) {
                p1 = fmaf(acc[i][j], w1[j], p1);
                p2 = fmaf(acc[i][j], w2[j], p2);
            }
#pragma unroll
            for (int o = 4; o >= 1; o >>= 1) {
                p1 += __shfl_xor_sync(0xffffffffu, p1, o);
                p2 += __shfl_xor_sync(0xffffffffu, p2, o);
            }
            if ((tx & 7) == 0) {
                g_f1[r * 4 + h] = p1;
                g_f2[r * 4 + h] = p2;
                mloc = fmaxf(mloc, p1);
            }
        }
        if ((tx & 7) == 0) atomicMax(&g_gmax_u[h], f_enc(mloc));
    }
}

// ---------------------------------------------------------------------------
// Per-node exp factorization: 65K exps total, zero in the hot loop.
// ---------------------------------------------------------------------------
__global__ __launch_bounds__(256) void precompute_kernel()
{
    const int n = blockIdx.x * 256 + threadIdx.x;
    float4 f1 = *(const float4*)&g_f1[n * 4];
    float4 f2 = *(const float4*)&g_f2[n * 4];
    const float f1a[4] = {f1.x, f1.y, f1.z, f1.w};
    const float f2a[4] = {f2.x, f2.y, f2.z, f2.w};
#pragma unroll
    for (int h = 0; h < NHEAD; h++) {
        float g = f_dec(g_gmax_u[h]);
        float d = f1a[h] - g;
        g_E1[n * 8 + h * 2 + 0] = __expf(d);
        g_E1[n * 8 + h * 2 + 1] = __expf(0.2f * d);
        float l = g + f2a[h];
        float M = fmaxf(l, 0.2f * l);
        float4 rc;
        rc.x = __expf(l - M);          // F2p
        rc.y = __expf(0.2f * l - M);   // F2n
        rc.z = __expf(-l);             // T: E1p >= T  <=>  f1[m]+f2[n] >= 0
        rc.w = 0.f;
        *(float4*)&g_rowc[n * 16 + h * 4] = rc;
    }
}

// ---------------------------------------------------------------------------
// Aggregation, occupancy-optimized: warp per row, NO e-phase / s_em staging.
// SMEM is only s_m (3KB) -> occupancy limited by regs; launch_bounds(128,10)
// targets <=51 regs (40 warps/SM vs 32 before). Each lane recomputes its own
// head's e in the gather from a broadcast float2 E1 load (L2-hot 256KB) +
// compare-select-mul. Gather unrolled 4 (independent LDS+LDG chains).
// ---------------------------------------------------------------------------
#define CCAP 192   // max edges per 2048-col chunk (mean 102, sd ~10)

__global__ __launch_bounds__(128, 10) void aggregate_kernel(
    const float* __restrict__ adj, float* __restrict__ out)
{
    __shared__ int s_m[4][CCAP];

    const int warp = threadIdx.x >> 5;
    const int lane = threadIdx.x & 31;
    const int n = blockIdx.x * 4 + warp;
    const int h = lane >> 3;

    // own-head row constants only (3 regs)
    const float4 rc = *(const float4*)&g_rowc[n * 16 + h * 4];
    const float F2p = rc.x, F2n = rc.y, Tt = rc.z;

    const char* supb = (const char*)g_support16 + h * 128 + (lane & 7) * 16;
    float ax0 = 0.f, ay0 = 0.f, ax1 = 0.f, ay1 = 0.f;
    float ax2 = 0.f, ay2 = 0.f, ax3 = 0.f, ay3 = 0.f;
    float denom = 0.f;

    const float4* arow = reinterpret_cast<const float4*>(adj + (size_t)n * NROWS);
    const unsigned lt = (1u << lane) - 1u;

    for (int c0 = 0; c0 < NROWS; c0 += 2048) {
        int cnt = 0;
        // ---- scan + warp compaction (order-free; sum is commutative) ----
#pragma unroll 4
        for (int j = 0; j < 16; j++) {
            float4 a4 = __ldcs(&arow[(c0 >> 2) + j * 32 + lane]);
            int col = c0 + (j * 32 + lane) * 4;
            unsigned b;
            b = __ballot_sync(0xffffffffu, a4.x != 0.f);
            if (a4.x != 0.f) { int p = cnt + __popc(b & lt); if (p < CCAP) s_m[warp][p] = col; }
            cnt += __popc(b);
            b = __ballot_sync(0xffffffffu, a4.y != 0.f);
            if (a4.y != 0.f) { int p = cnt + __popc(b & lt); if (p < CCAP) s_m[warp][p] = col + 1; }
            cnt += __popc(b);
            b = __ballot_sync(0xffffffffu, a4.z != 0.f);
            if (a4.z != 0.f) { int p = cnt + __popc(b & lt); if (p < CCAP) s_m[warp][p] = col + 2; }
            cnt += __popc(b);
            b = __ballot_sync(0xffffffffu, a4.w != 0.f);
            if (a4.w != 0.f) { int p = cnt + __popc(b & lt); if (p < CCAP) s_m[warp][p] = col + 3; }
            cnt += __popc(b);
        }
        cnt = min(cnt, CCAP);
        __syncwarp();

        // ---- gather + accumulate (e recomputed per lane, no exp) ----
        int i = 0;
        for (; i + 4 <= cnt; i += 4) {
#pragma unroll
            for (int u = 0; u < 4; u++) {
                int m = s_m[warp][i + u];
                float2 e1 = *(const float2*)&g_E1[m * 8 + h * 2];
                float e = (e1.x >= Tt) ? e1.x * F2p : e1.y * F2n;
                float4 raw = *(const float4*)(supb + ((size_t)m << 9));
                const __half2* hp = (const __half2*)&raw;
                float2 v0 = __half22float2(hp[0]);
                float2 v1 = __half22float2(hp[1]);
                float2 v2 = __half22float2(hp[2]);
                float2 v3 = __half22float2(hp[3]);
                ax0 = fmaf(e, v0.x, ax0); ay0 = fmaf(e, v0.y, ay0);
                ax1 = fmaf(e, v1.x, ax1); ay1 = fmaf(e, v1.y, ay1);
                ax2 = fmaf(e, v2.x, ax2); ay2 = fmaf(e, v2.y, ay2);
                ax3 = fmaf(e, v3.x, ax3); ay3 = fmaf(e, v3.y, ay3);
                denom += e;
            }
        }
        for (; i < cnt; i++) {
            int m = s_m[warp][i];
            float2 e1 = *(const float2*)&g_E1[m * 8 + h * 2];
            float e = (e1.x >= Tt) ? e1.x * F2p : e1.y * F2n;
            float4 raw = *(const float4*)(supb + ((size_t)m << 9));
            const __half2* hp = (const __half2*)&raw;
            float2 v0 = __half22float2(hp[0]);
            float2 v1 = __half22float2(hp[1]);
            float2 v2 = __half22float2(hp[2]);
            float2 v3 = __half22float2(hp[3]);
            ax0 = fmaf(e, v0.x, ax0); ay0 = fmaf(e, v0.y, ay0);
            ax1 = fmaf(e, v1.x, ax1); ay1 = fmaf(e, v1.y, ay1);
            ax2 = fmaf(e, v2.x, ax2); ay2 = fmaf(e, v2.y, ay2);
            ax3 = fmaf(e, v3.x, ax3); ay3 = fmaf(e, v3.y, ay3);
            denom += e;
        }
        __syncwarp();
    }

    const float inv = 1.0f / fmaxf(denom, 1e-30f);
    float* orow = out + (size_t)n * 256 + h * 64 + (lane & 7) * 8;
    float4 o0 = *(float4*)orow;
    float4 o1 = *(float4*)(orow + 4);
    o0.x += ax0 * inv; o0.y += ay0 * inv;
    o0.z += ax1 * inv; o0.w += ay1 * inv;
    o1.x += ax2 * inv; o1.y += ay2 * inv;
    o1.z += ax3 * inv; o1.w += ay3 * inv;
    *(float4*)orow = o0;
    *(float4*)(orow + 4) = o1;
}

// ---------------------------------------------------------------------------
extern "C" void kernel_launch(void* const* d_in, const int* in_sizes, int n_in,
                              void* d_out, int out_size)
{
    const float* inputs = (const float*)d_in[0];
    const float* adj    = (const float*)d_in[1];
    const float* weight = (const float*)d_in[2];
    const float* wu     = (const float*)d_in[3];
    const float* wv     = (const float*)d_in[4];
    const float* bias   = (const float*)d_in[5];
    const float* projw  = (const float*)d_in[6];
    const float* projb  = (const float*)d_in[7];
    float* out = (float*)d_out;

    init_kernel<<<1, 32>>>();

    dim3 grid_gemm(2, 64, 2);
    gemm_fused<<<grid_gemm, 256>>>(inputs, weight, projw, projb, bias, wu, wv, out);
    precompute_kernel<<<NROWS / 256, 256>>>();
    aggregate_kernel<<<NROWS / 4, 128>>>(adj, out);
}